// round 5
// baseline (speedup 1.0000x reference)
#include <cuda_runtime.h>
#include <cstdint>

// FurthestPointsSample: x [B,3,N] f32 -> out [B,3,1024] f32. B=16, N=65536.
// 8-CTA cluster per batch; points register-resident (8/thread, packed f32x2)
// + SMEM mirror. Per round: f32x2 dist update, REDUX reductions, then a
// mbarrier-FREE exchange: weak remote smem stores {x,y}{z,dist} + release
// seq word; each CTA's reducer warp (warp 31) polls its OWN smem seq words
// with acquire loads. No tx-event serialization, no TRYWAIT wakeup.

#define N_PTS   65536
#define CLUSTER 8
#define PPC     (N_PTS / CLUSTER)   // 8192
#define THREADS 1024
#define PPT     (PPC / THREADS)     // 8
#define NPAIR   (PPT / 2)           // 4
#define NPOINTS 1024
#define RWID    31                  // reducer warp (hi-wid arbiter priority)

__device__ __forceinline__ unsigned ctarank() {
    unsigned r; asm("mov.u32 %0, %%cluster_ctarank;" : "=r"(r)); return r;
}
__device__ __forceinline__ void cluster_sync_all() {
    asm volatile("barrier.cluster.arrive.aligned;\n\t"
                 "barrier.cluster.wait.aligned;" ::: "memory");
}
__device__ __forceinline__ unsigned mapa_sh(unsigned addr, unsigned rank) {
    unsigned r;
    asm("mapa.shared::cluster.u32 %0, %1, %2;" : "=r"(r) : "r"(addr), "r"(rank));
    return r;
}
__device__ __forceinline__ unsigned long long addx2(unsigned long long a, unsigned long long b) {
    unsigned long long r; asm("add.rn.f32x2 %0, %1, %2;" : "=l"(r) : "l"(a), "l"(b)); return r;
}
__device__ __forceinline__ unsigned long long mulx2(unsigned long long a, unsigned long long b) {
    unsigned long long r; asm("mul.rn.f32x2 %0, %1, %2;" : "=l"(r) : "l"(a), "l"(b)); return r;
}
__device__ __forceinline__ unsigned long long packf2(float lo, float hi) {
    unsigned long long r; asm("mov.b64 %0, {%1, %2};" : "=l"(r) : "f"(lo), "f"(hi)); return r;
}
__device__ __forceinline__ void unpackf2(unsigned long long v, float& lo, float& hi) {
    asm("mov.b64 {%0, %1}, %2;" : "=f"(lo), "=f"(hi) : "l"(v));
}
__device__ __forceinline__ unsigned long long pack_fu(float z, unsigned hi) {
    unsigned long long r; asm("mov.b64 %0, {%1, %2};" : "=l"(r) : "f"(z), "r"(hi)); return r;
}
__device__ __forceinline__ void unpack_fu(unsigned long long v, float& z, unsigned& hi) {
    asm("mov.b64 {%0, %1}, %2;" : "=f"(z), "=r"(hi) : "l"(v));
}
// Weak remote-smem store (data words).
__device__ __forceinline__ void st_clu_u64(unsigned addr, unsigned long long v) {
    asm volatile("st.shared::cluster.b64 [%0], %1;" :: "r"(addr), "l"(v) : "memory");
}
// Release store (seq word) — orders the prior weak stores before it.
__device__ __forceinline__ void st_rel_u32(unsigned addr, unsigned v) {
    asm volatile("st.release.cluster.shared::cluster.b32 [%0], %1;"
                 :: "r"(addr), "r"(v) : "memory");
}
// Acquire load of a local smem seq word written by a cluster peer.
__device__ __forceinline__ unsigned ld_acq_u32(unsigned addr) {
    unsigned v;
    asm volatile("ld.acquire.cluster.shared::cta.b32 %0, [%1];"
                 : "=r"(v) : "r"(addr) : "memory");
    return v;
}
__device__ __forceinline__ unsigned long long ld_sh_u64(unsigned addr) {
    unsigned long long v;
    asm volatile("ld.shared.b64 %0, [%1];" : "=l"(v) : "r"(addr) : "memory");
    return v;
}

extern __shared__ float smem_dyn[];   // xs[8192] ys[8192] zs[8192] = 96 KB

__global__ void __launch_bounds__(THREADS, 1) __cluster_dims__(CLUSTER, 1, 1)
fps_cluster_kernel(const float* __restrict__ x, float* __restrict__ out)
{
    __shared__ unsigned long long warp_key[32];
    // 32-byte slots: [x f32][y f32] @0 | [z f32][distbits u32] @8 | [seq u32] @16 | pad
    __shared__ __align__(16) unsigned slotw[2][CLUSTER][8];
    __shared__ float4 bcast[2];

    const unsigned r    = ctarank();
    const unsigned b    = blockIdx.x / CLUSTER;
    const unsigned tid  = threadIdx.x;
    const unsigned lane = tid & 31u;
    const unsigned wid  = tid >> 5;

    const float* __restrict__ xb = x + (size_t)b * 3u * N_PTS;
    const float* __restrict__ yb = xb + N_PTS;
    const float* __restrict__ zb = xb + 2 * N_PTS;
    float* __restrict__ ob = out + (size_t)b * 3u * NPOINTS;

    float* xs = smem_dyn;
    float* ys = xs + PPC;
    float* zs = ys + PPC;

    const unsigned slot_base = (unsigned)__cvta_generic_to_shared(&slotw[0][0][0]);

    // Zero the seq words (polled for round numbers starting at 1).
    if (tid < 2 * CLUSTER) slotw[tid >> 3][tid & 7][4] = 0u;

    // Hoisted remote slot addresses: lane t (t<8) targets rank t, slot r.
    // My slot index within each destination is my rank r, for both parities.
    unsigned rs0 = 0, rs1 = 0;
    if (lane < CLUSTER) {
        rs0 = mapa_sh(slot_base + (0 * CLUSTER + r) * 32u, lane);
        rs1 = mapa_sh(slot_base + (1 * CLUSTER + r) * 32u, lane);
    }
    // Local poll addresses (seq word of slot lane&7, per parity).
    const unsigned ps0 = slot_base + (0 * CLUSTER + (lane & 7u)) * 32u + 16u;
    const unsigned ps1 = slot_base + (1 * CLUSTER + (lane & 7u)) * 32u + 16u;

    // Load points into registers (packed pairs) + SMEM mirror.
    unsigned long long px2[NPAIR], py2[NPAIR], pz2[NPAIR];
    float dist[PPT];
    const unsigned gbase = r * PPC + tid;
#pragma unroll
    for (int p = 0; p < NPAIR; p++) {
        unsigned g0 = gbase + (unsigned)(2 * p) * THREADS;
        unsigned g1 = g0 + THREADS;
        float x0 = xb[g0], x1 = xb[g1];
        float y0 = yb[g0], y1 = yb[g1];
        float z0 = zb[g0], z1 = zb[g1];
        px2[p] = packf2(x0, x1); py2[p] = packf2(y0, y1); pz2[p] = packf2(z0, z1);
        unsigned l0 = tid + (unsigned)(2 * p) * THREADS, l1 = l0 + THREADS;
        xs[l0] = x0; xs[l1] = x1; ys[l0] = y0; ys[l1] = y1; zs[l0] = z0; zs[l1] = z1;
        dist[2 * p] = 1e10f; dist[2 * p + 1] = 1e10f;
    }
    __syncthreads();
    cluster_sync_all();   // peers' seq-zeroing + mirrors done before any remote store

    // First selected point: index 0 (reference convention).
    float fx = __ldg(xb + 0), fy = __ldg(yb + 0), fz = __ldg(zb + 0);
    if (r == 0 && tid == 0) { ob[0] = fx; ob[NPOINTS] = fy; ob[2 * NPOINTS] = fz; }
    unsigned long long nlx2 = packf2(-fx, -fx);
    unsigned long long nly2 = packf2(-fy, -fy);
    unsigned long long nlz2 = packf2(-fz, -fz);

    for (int it = 1; it < NPOINTS; it++) {
        const int par = it & 1;

        // ---- dist update + thread-local argmax (bit-exact, first occurrence) ----
        float bestd = -1.0f; int bestj = 0;
#pragma unroll
        for (int p = 0; p < NPAIR; p++) {
            unsigned long long dx = addx2(px2[p], nlx2);
            unsigned long long dy = addx2(py2[p], nly2);
            unsigned long long dz = addx2(pz2[p], nlz2);
            unsigned long long s  = addx2(addx2(mulx2(dx, dx), mulx2(dy, dy)), mulx2(dz, dz));
            float s0, s1; unpackf2(s, s0, s1);
            float nd0 = fminf(dist[2 * p], s0);     dist[2 * p]     = nd0;
            float nd1 = fminf(dist[2 * p + 1], s1); dist[2 * p + 1] = nd1;
            bool c0 = nd0 > bestd; bestd = c0 ? nd0 : bestd; bestj = c0 ? 2 * p : bestj;
            bool c1 = nd1 > bestd; bestd = c1 ? nd1 : bestd; bestj = c1 ? 2 * p + 1 : bestj;
        }

        // ---- warp reduction: max dist bits, then min global index ----
        unsigned bits = __float_as_uint(bestd);
        unsigned wmax = __reduce_max_sync(0xffffffffu, bits);
        unsigned g    = gbase + (unsigned)bestj * THREADS;
        unsigned cand = (bits == wmax) ? ~g : 0u;
        unsigned wi   = __reduce_max_sync(0xffffffffu, cand);
        if (lane == 0)
            warp_key[wid] = ((unsigned long long)wmax << 32) | wi;
        __syncthreads();

        if (wid == RWID) {
            // ---- block reduction over 32 warp keys ----
            unsigned long long k = warp_key[lane];
            unsigned hb = (unsigned)(k >> 32);
            unsigned hm = __reduce_max_sync(0xffffffffu, hb);
            unsigned lo = (hb == hm) ? (unsigned)k : 0u;
            unsigned lm = __reduce_max_sync(0xffffffffu, lo);

            // ---- push {x,y | z,dist | seq} (release) to every CTA ----
            if (lane < CLUSTER) {
                unsigned local = (~lm) & (PPC - 1);     // block winner, CTA-local
                float wx = xs[local], wy = ys[local], wz = zs[local];
                unsigned rslot = par ? rs1 : rs0;
                st_clu_u64(rslot,     packf2(wx, wy));
                st_clu_u64(rslot + 8, pack_fu(wz, hm));
                st_rel_u32(rslot + 16, (unsigned)it);
            }

            // ---- poll OWN smem seq words until all 8 sources delivered ----
            const unsigned pseq = par ? ps1 : ps0;
            while (__ballot_sync(0xffffffffu, ld_acq_u32(pseq) != (unsigned)it)) {}

            // ---- reduce the 8 slots; min slot == min rank == min global idx ----
            unsigned myslot = slot_base + (unsigned)(par * CLUSTER + (int)(lane & 7u)) * 32u;
            unsigned long long w0 = ld_sh_u64(myslot);       // {x, y}
            unsigned long long w1 = ld_sh_u64(myslot + 8);   // {z, distbits}
            float sz; unsigned db; unpack_fu(w1, sz, db);
            unsigned m   = __reduce_max_sync(0xffffffffu, db);
            unsigned bal = __ballot_sync(0xffffffffu, (lane < CLUSTER) && (db == m));
            unsigned winlane = (unsigned)(__ffs(bal) - 1);
            if (lane == winlane) {
                float sx, sy; unpackf2(w0, sx, sy);
                bcast[par] = make_float4(sx, sy, sz, 0.0f);
                if (r == 0) {
                    ob[it] = sx; ob[NPOINTS + it] = sy; ob[2 * NPOINTS + it] = sz;
                }
            }
        }
        __syncthreads();

        float4 w = bcast[par];
        nlx2 = packf2(-w.x, -w.x);
        nly2 = packf2(-w.y, -w.y);
        nlz2 = packf2(-w.z, -w.z);
    }
}

extern "C" void kernel_launch(void* const* d_in, const int* in_sizes, int n_in,
                              void* d_out, int out_size)
{
    const float* x = (const float*)d_in[0];
    float* out = (float*)d_out;
    int B = in_sizes[0] / (3 * N_PTS);   // 16
    size_t dyn = 3 * PPC * sizeof(float);   // 96 KB
    cudaFuncSetAttribute(fps_cluster_kernel,
                         cudaFuncAttributeMaxDynamicSharedMemorySize, (int)dyn);
    dim3 grid(B * CLUSTER), block(THREADS);
    fps_cluster_kernel<<<grid, block, dyn>>>(x, out);
}

// round 6
// speedup vs baseline: 1.3925x; 1.3925x over previous
#include <cuda_runtime.h>
#include <cstdint>

// FurthestPointsSample: x [B,3,N] f32 -> out [B,3,1024] f32. B=16, N=65536.
// 8-CTA cluster per batch; points register-resident (8/thread, packed f32x2)
// + SMEM mirror. Per round: f32x2 dist update, REDUX reductions, 16-byte
// st.async all-to-all {x,y}->mbarA {z,distbits}->mbarB (two barriers so the
// two 8-event tx-accounting streams serialize in parallel), warp0 waits both,
// reduces slots, smem-broadcasts. Tie-break = slot position (contiguous ranks).

#define N_PTS   65536
#define CLUSTER 8
#define PPC     (N_PTS / CLUSTER)   // 8192
#define THREADS 1024
#define PPT     (PPC / THREADS)     // 8
#define NPAIR   (PPT / 2)           // 4
#define NPOINTS 1024
#define MSG_A   8                   // bytes per source on barrier A ({x,y})
#define MSG_B   8                   // bytes per source on barrier B ({z,distbits})

__device__ __forceinline__ unsigned ctarank() {
    unsigned r; asm("mov.u32 %0, %%cluster_ctarank;" : "=r"(r)); return r;
}
__device__ __forceinline__ void cluster_sync_all() {
    asm volatile("barrier.cluster.arrive.aligned;\n\t"
                 "barrier.cluster.wait.aligned;" ::: "memory");
}
__device__ __forceinline__ unsigned mapa_sh(unsigned addr, unsigned rank) {
    unsigned r;
    asm("mapa.shared::cluster.u32 %0, %1, %2;" : "=r"(r) : "r"(addr), "r"(rank));
    return r;
}
__device__ __forceinline__ unsigned long long addx2(unsigned long long a, unsigned long long b) {
    unsigned long long r; asm("add.rn.f32x2 %0, %1, %2;" : "=l"(r) : "l"(a), "l"(b)); return r;
}
__device__ __forceinline__ unsigned long long mulx2(unsigned long long a, unsigned long long b) {
    unsigned long long r; asm("mul.rn.f32x2 %0, %1, %2;" : "=l"(r) : "l"(a), "l"(b)); return r;
}
__device__ __forceinline__ unsigned long long packf2(float lo, float hi) {
    unsigned long long r; asm("mov.b64 %0, {%1, %2};" : "=l"(r) : "f"(lo), "f"(hi)); return r;
}
__device__ __forceinline__ void unpackf2(unsigned long long v, float& lo, float& hi) {
    asm("mov.b64 {%0, %1}, %2;" : "=f"(lo), "=f"(hi) : "l"(v));
}
__device__ __forceinline__ unsigned long long pack_fu(float z, unsigned hi) {
    unsigned long long r; asm("mov.b64 %0, {%1, %2};" : "=l"(r) : "f"(z), "r"(hi)); return r;
}
__device__ __forceinline__ void st_async_u64(unsigned addr, unsigned long long v, unsigned mbar) {
    asm volatile("st.async.shared::cluster.mbarrier::complete_tx::bytes.b64 [%0], %1, [%2];"
                 :: "r"(addr), "l"(v), "r"(mbar) : "memory");
}
__device__ __forceinline__ void mbar_init(unsigned addr, unsigned cnt) {
    asm volatile("mbarrier.init.shared.b64 [%0], %1;" :: "r"(addr), "r"(cnt) : "memory");
}
__device__ __forceinline__ void mbar_expect_tx(unsigned addr, unsigned tx) {
    asm volatile("mbarrier.arrive.expect_tx.shared.b64 _, [%0], %1;"
                 :: "r"(addr), "r"(tx) : "memory");
}
__device__ __forceinline__ void mbar_wait(unsigned addr, unsigned phase) {
    asm volatile(
        "{\n\t.reg .pred P;\n\t"
        "LAB_%=:\n\t"
        "mbarrier.try_wait.parity.acquire.cta.shared::cta.b64 P, [%0], %1, 0x989680;\n\t"
        "@!P bra LAB_%=;\n\t}"
        :: "r"(addr), "r"(phase) : "memory");
}

extern __shared__ float smem_dyn[];   // xs[8192] ys[8192] zs[8192] = 96 KB

__global__ void __launch_bounds__(THREADS, 1) __cluster_dims__(CLUSTER, 1, 1)
fps_cluster_kernel(const float* __restrict__ x, float* __restrict__ out)
{
    __shared__ unsigned long long warp_key[32];
    // 16-byte slots: [x f32][y f32][z f32][distbits u32]
    __shared__ __align__(16) float slotmem[2][CLUSTER][4];
    __shared__ float4 bcast[2];
    // mbar[par][0] = barrier A ({x,y} events), mbar[par][1] = barrier B.
    __shared__ __align__(8) unsigned long long mbar[2][2];

    const unsigned r    = ctarank();
    const unsigned b    = blockIdx.x / CLUSTER;
    const unsigned tid  = threadIdx.x;
    const unsigned lane = tid & 31u;
    const unsigned wid  = tid >> 5;

    const float* __restrict__ xb = x + (size_t)b * 3u * N_PTS;
    const float* __restrict__ yb = xb + N_PTS;
    const float* __restrict__ zb = xb + 2 * N_PTS;
    float* __restrict__ ob = out + (size_t)b * 3u * NPOINTS;

    float* xs = smem_dyn;
    float* ys = xs + PPC;
    float* zs = ys + PPC;

    const unsigned slot_base = (unsigned)__cvta_generic_to_shared(&slotmem[0][0][0]);
    const unsigned bar_base  = (unsigned)__cvta_generic_to_shared(&mbar[0][0]);

    if (tid < 4) mbar_init(bar_base + tid * 8u, 1);

    // Load points into registers (packed pairs) + SMEM mirror.
    unsigned long long px2[NPAIR], py2[NPAIR], pz2[NPAIR];
    float dist[PPT];
    const unsigned gbase = r * PPC + tid;
#pragma unroll
    for (int p = 0; p < NPAIR; p++) {
        unsigned g0 = gbase + (unsigned)(2 * p) * THREADS;
        unsigned g1 = g0 + THREADS;
        float x0 = xb[g0], x1 = xb[g1];
        float y0 = yb[g0], y1 = yb[g1];
        float z0 = zb[g0], z1 = zb[g1];
        px2[p] = packf2(x0, x1); py2[p] = packf2(y0, y1); pz2[p] = packf2(z0, z1);
        unsigned l0 = tid + (unsigned)(2 * p) * THREADS, l1 = l0 + THREADS;
        xs[l0] = x0; xs[l1] = x1; ys[l0] = y0; ys[l1] = y1; zs[l0] = z0; zs[l1] = z1;
        dist[2 * p] = 1e10f; dist[2 * p + 1] = 1e10f;
    }
    __syncthreads();
    cluster_sync_all();   // peers' mbarriers initialized before any st.async

    // First selected point: index 0 (reference convention).
    float fx = __ldg(xb + 0), fy = __ldg(yb + 0), fz = __ldg(zb + 0);
    if (r == 0 && tid == 0) { ob[0] = fx; ob[NPOINTS] = fy; ob[2 * NPOINTS] = fz; }
    unsigned long long nlx2 = packf2(-fx, -fx);
    unsigned long long nly2 = packf2(-fy, -fy);
    unsigned long long nlz2 = packf2(-fz, -fz);

    unsigned ph0 = 0, ph1 = 0;

    for (int it = 1; it < NPOINTS; it++) {
        const int par = it & 1;
        const unsigned barA = bar_base + (unsigned)par * 16u;
        const unsigned barB = barA + 8u;

        // Arm both barriers early (off the critical tail).
        if (tid == 0) {
            mbar_expect_tx(barA, CLUSTER * MSG_A);
            mbar_expect_tx(barB, CLUSTER * MSG_B);
        }

        // ---- dist update + thread-local argmax (bit-exact, first occurrence) ----
        float bestd = -1.0f; int bestj = 0;
#pragma unroll
        for (int p = 0; p < NPAIR; p++) {
            unsigned long long dx = addx2(px2[p], nlx2);
            unsigned long long dy = addx2(py2[p], nly2);
            unsigned long long dz = addx2(pz2[p], nlz2);
            unsigned long long s  = addx2(addx2(mulx2(dx, dx), mulx2(dy, dy)), mulx2(dz, dz));
            float s0, s1; unpackf2(s, s0, s1);
            float nd0 = fminf(dist[2 * p], s0);     dist[2 * p]     = nd0;
            float nd1 = fminf(dist[2 * p + 1], s1); dist[2 * p + 1] = nd1;
            bool c0 = nd0 > bestd; bestd = c0 ? nd0 : bestd; bestj = c0 ? 2 * p : bestj;
            bool c1 = nd1 > bestd; bestd = c1 ? nd1 : bestd; bestj = c1 ? 2 * p + 1 : bestj;
        }

        // ---- warp reduction: max dist bits, then min global index ----
        unsigned bits = __float_as_uint(bestd);
        unsigned wmax = __reduce_max_sync(0xffffffffu, bits);
        unsigned g    = gbase + (unsigned)bestj * THREADS;
        unsigned cand = (bits == wmax) ? ~g : 0u;
        unsigned wi   = __reduce_max_sync(0xffffffffu, cand);
        if (lane == 0)
            warp_key[wid] = ((unsigned long long)wmax << 32) | wi;
        __syncthreads();

        if (wid == 0) {
            // ---- block reduction over 32 warp keys ----
            unsigned long long k = warp_key[lane];
            unsigned hb = (unsigned)(k >> 32);
            unsigned hm = __reduce_max_sync(0xffffffffu, hb);
            unsigned lo = (hb == hm) ? (unsigned)k : 0u;
            unsigned lm = __reduce_max_sync(0xffffffffu, lo);

            // ---- push {x,y}->barA  {z,distbits}->barB to every CTA ----
            if (lane < CLUSTER) {
                unsigned local = (~lm) & (PPC - 1);     // block winner, CTA-local
                float wx = xs[local], wy = ys[local], wz = zs[local];
                unsigned lslot = slot_base + (unsigned)(par * CLUSTER + (int)r) * 16u;
                unsigned rslot = mapa_sh(lslot, lane);
                unsigned rbarA = mapa_sh(barA, lane);
                unsigned rbarB = mapa_sh(barB, lane);
                st_async_u64(rslot,     packf2(wx, wy), rbarA);
                st_async_u64(rslot + 8, pack_fu(wz, hm), rbarB);
            }

            // ---- wait both barriers (B's events stream during A's wait) ----
            unsigned ph = par ? ph1 : ph0;
            mbar_wait(barA, ph);
            mbar_wait(barB, ph);

            // ---- reduce the 8 slots; min slot == min rank == min global idx ----
            float4 s = *(const float4*)&slotmem[par][lane & (CLUSTER - 1)][0];
            unsigned db = __float_as_uint(s.w);
            unsigned m  = __reduce_max_sync(0xffffffffu, db);
            unsigned bal = __ballot_sync(0xffffffffu, (lane < CLUSTER) && (db == m));
            if (lane == (unsigned)(__ffs(bal) - 1)) {
                bcast[par] = s;
                if (r == 0) {
                    ob[it] = s.x; ob[NPOINTS + it] = s.y; ob[2 * NPOINTS + it] = s.z;
                }
            }
        }
        __syncthreads();

        float4 w = bcast[par];
        nlx2 = packf2(-w.x, -w.x);
        nly2 = packf2(-w.y, -w.y);
        nlz2 = packf2(-w.z, -w.z);
        if (par) ph1 ^= 1; else ph0 ^= 1;
    }
}

extern "C" void kernel_launch(void* const* d_in, const int* in_sizes, int n_in,
                              void* d_out, int out_size)
{
    const float* x = (const float*)d_in[0];
    float* out = (float*)d_out;
    int B = in_sizes[0] / (3 * N_PTS);   // 16
    size_t dyn = 3 * PPC * sizeof(float);   // 96 KB
    cudaFuncSetAttribute(fps_cluster_kernel,
                         cudaFuncAttributeMaxDynamicSharedMemorySize, (int)dyn);
    dim3 grid(B * CLUSTER), block(THREADS);
    fps_cluster_kernel<<<grid, block, dyn>>>(x, out);
}

// round 8
// speedup vs baseline: 1.4239x; 1.0225x over previous
#include <cuda_runtime.h>
#include <cstdint>

// FurthestPointsSample: x [B,3,N] f32 -> out [B,3,1024] f32. B=16, N=65536.
// 8-CTA cluster per batch; points register-resident (8/thread, packed f32x2)
// + SMEM mirror. Per round: f32x2 dist update + inline select argmax (R4),
// REDUX reductions, 16-byte st.async all-to-all {x,y}{z,distbits} on ONE
// mbarrier per parity; ALL warps sleep on the mbarrier and each reduces the
// 8 slots itself (no broadcast, no second block barrier). Hoisted mapa.

#define N_PTS   65536
#define CLUSTER 8
#define PPC     (N_PTS / CLUSTER)   // 8192
#define THREADS 1024
#define PPT     (PPC / THREADS)     // 8
#define NPAIR   (PPT / 2)           // 4
#define NPOINTS 1024
#define MSG_TX  16                  // bytes per source CTA: 8 (x,y) + 8 (z,distbits)

__device__ __forceinline__ unsigned ctarank() {
    unsigned r; asm("mov.u32 %0, %%cluster_ctarank;" : "=r"(r)); return r;
}
__device__ __forceinline__ void cluster_sync_all() {
    asm volatile("barrier.cluster.arrive.aligned;\n\t"
                 "barrier.cluster.wait.aligned;" ::: "memory");
}
__device__ __forceinline__ unsigned mapa_sh(unsigned addr, unsigned rank) {
    unsigned r;
    asm("mapa.shared::cluster.u32 %0, %1, %2;" : "=r"(r) : "r"(addr), "r"(rank));
    return r;
}
__device__ __forceinline__ unsigned long long addx2(unsigned long long a, unsigned long long b) {
    unsigned long long r; asm("add.rn.f32x2 %0, %1, %2;" : "=l"(r) : "l"(a), "l"(b)); return r;
}
__device__ __forceinline__ unsigned long long mulx2(unsigned long long a, unsigned long long b) {
    unsigned long long r; asm("mul.rn.f32x2 %0, %1, %2;" : "=l"(r) : "l"(a), "l"(b)); return r;
}
__device__ __forceinline__ unsigned long long packf2(float lo, float hi) {
    unsigned long long r; asm("mov.b64 %0, {%1, %2};" : "=l"(r) : "f"(lo), "f"(hi)); return r;
}
__device__ __forceinline__ void unpackf2(unsigned long long v, float& lo, float& hi) {
    asm("mov.b64 {%0, %1}, %2;" : "=f"(lo), "=f"(hi) : "l"(v));
}
__device__ __forceinline__ unsigned long long pack_fu(float z, unsigned hi) {
    unsigned long long r; asm("mov.b64 %0, {%1, %2};" : "=l"(r) : "f"(z), "r"(hi)); return r;
}
__device__ __forceinline__ void st_async_u64(unsigned addr, unsigned long long v, unsigned mbar) {
    asm volatile("st.async.shared::cluster.mbarrier::complete_tx::bytes.b64 [%0], %1, [%2];"
                 :: "r"(addr), "l"(v), "r"(mbar) : "memory");
}
__device__ __forceinline__ void mbar_init(unsigned addr, unsigned cnt) {
    asm volatile("mbarrier.init.shared.b64 [%0], %1;" :: "r"(addr), "r"(cnt) : "memory");
}
__device__ __forceinline__ void mbar_expect_tx(unsigned addr, unsigned tx) {
    asm volatile("mbarrier.arrive.expect_tx.shared.b64 _, [%0], %1;"
                 :: "r"(addr), "r"(tx) : "memory");
}
__device__ __forceinline__ void mbar_wait(unsigned addr, unsigned phase) {
    asm volatile(
        "{\n\t.reg .pred P;\n\t"
        "LAB_%=:\n\t"
        "mbarrier.try_wait.parity.acquire.cta.shared::cta.b64 P, [%0], %1, 0x989680;\n\t"
        "@!P bra LAB_%=;\n\t}"
        :: "r"(addr), "r"(phase) : "memory");
}

extern __shared__ float smem_dyn[];   // xs[8192] ys[8192] zs[8192] = 96 KB

__global__ void __launch_bounds__(THREADS, 1) __cluster_dims__(CLUSTER, 1, 1)
fps_cluster_kernel(const float* __restrict__ x, float* __restrict__ out)
{
    __shared__ unsigned long long warp_key[32];
    // 16-byte slots: [x f32][y f32][z f32][distbits u32]
    __shared__ __align__(16) float slotmem[2][CLUSTER][4];
    __shared__ __align__(8) unsigned long long mbar[2];

    const unsigned r    = ctarank();
    const unsigned b    = blockIdx.x / CLUSTER;
    const unsigned tid  = threadIdx.x;
    const unsigned lane = tid & 31u;
    const unsigned wid  = tid >> 5;

    const float* __restrict__ xb = x + (size_t)b * 3u * N_PTS;
    const float* __restrict__ yb = xb + N_PTS;
    const float* __restrict__ zb = xb + 2 * N_PTS;
    float* __restrict__ ob = out + (size_t)b * 3u * NPOINTS;

    float* xs = smem_dyn;
    float* ys = xs + PPC;
    float* zs = ys + PPC;

    const unsigned slot_base = (unsigned)__cvta_generic_to_shared(&slotmem[0][0][0]);
    const unsigned bar_base  = (unsigned)__cvta_generic_to_shared(&mbar[0]);

    if (tid == 0) { mbar_init(bar_base, 1); mbar_init(bar_base + 8, 1); }

    // Hoisted remote addresses (lane t < 8 targets rank t; my slot index = r).
    unsigned rs0 = 0, rs1 = 0, rb0 = 0, rb1 = 0;
    if (lane < CLUSTER) {
        rs0 = mapa_sh(slot_base + (0 * CLUSTER + r) * 16u, lane);
        rs1 = mapa_sh(slot_base + (1 * CLUSTER + r) * 16u, lane);
        rb0 = mapa_sh(bar_base,      lane);
        rb1 = mapa_sh(bar_base + 8u, lane);
    }

    // Load points into registers (packed pairs) + SMEM mirror.
    unsigned long long px2[NPAIR], py2[NPAIR], pz2[NPAIR];
    float dist[PPT];
    const unsigned gbase = r * PPC + tid;
#pragma unroll
    for (int p = 0; p < NPAIR; p++) {
        unsigned g0 = gbase + (unsigned)(2 * p) * THREADS;
        unsigned g1 = g0 + THREADS;
        float x0 = xb[g0], x1 = xb[g1];
        float y0 = yb[g0], y1 = yb[g1];
        float z0 = zb[g0], z1 = zb[g1];
        px2[p] = packf2(x0, x1); py2[p] = packf2(y0, y1); pz2[p] = packf2(z0, z1);
        unsigned l0 = tid + (unsigned)(2 * p) * THREADS, l1 = l0 + THREADS;
        xs[l0] = x0; xs[l1] = x1; ys[l0] = y0; ys[l1] = y1; zs[l0] = z0; zs[l1] = z1;
        dist[2 * p] = 1e10f; dist[2 * p + 1] = 1e10f;
    }
    __syncthreads();
    cluster_sync_all();   // peers' mbarriers initialized before any st.async

    // First selected point: index 0 (reference convention).
    float fx = __ldg(xb + 0), fy = __ldg(yb + 0), fz = __ldg(zb + 0);
    if (r == 0 && tid == 0) { ob[0] = fx; ob[NPOINTS] = fy; ob[2 * NPOINTS] = fz; }
    unsigned long long nlx2 = packf2(-fx, -fx);
    unsigned long long nly2 = packf2(-fy, -fy);
    unsigned long long nlz2 = packf2(-fz, -fz);

    unsigned ph0 = 0, ph1 = 0;

    for (int it = 1; it < NPOINTS; it++) {
        const int par = it & 1;
        const unsigned barp = bar_base + (unsigned)par * 8u;

        // Arm this round's barrier early (off the critical tail).
        if (tid == 0) mbar_expect_tx(barp, CLUSTER * MSG_TX);

        // ---- dist update + thread-local argmax (bit-exact, first occurrence) ----
        float bestd = -1.0f; int bestj = 0;
#pragma unroll
        for (int p = 0; p < NPAIR; p++) {
            unsigned long long dx = addx2(px2[p], nlx2);
            unsigned long long dy = addx2(py2[p], nly2);
            unsigned long long dz = addx2(pz2[p], nlz2);
            unsigned long long s  = addx2(addx2(mulx2(dx, dx), mulx2(dy, dy)), mulx2(dz, dz));
            float s0, s1; unpackf2(s, s0, s1);
            float nd0 = fminf(dist[2 * p], s0);     dist[2 * p]     = nd0;
            float nd1 = fminf(dist[2 * p + 1], s1); dist[2 * p + 1] = nd1;
            bool c0 = nd0 > bestd; bestd = c0 ? nd0 : bestd; bestj = c0 ? 2 * p : bestj;
            bool c1 = nd1 > bestd; bestd = c1 ? nd1 : bestd; bestj = c1 ? 2 * p + 1 : bestj;
        }

        // ---- warp reduction: max dist bits, then min global index ----
        unsigned bits = __float_as_uint(bestd);
        unsigned wmax = __reduce_max_sync(0xffffffffu, bits);
        unsigned g    = gbase + (unsigned)bestj * THREADS;
        unsigned cand = (bits == wmax) ? ~g : 0u;
        unsigned wi   = __reduce_max_sync(0xffffffffu, cand);
        if (lane == 0)
            warp_key[wid] = ((unsigned long long)wmax << 32) | wi;
        __syncthreads();

        if (wid == 0) {
            // ---- block reduction over 32 warp keys ----
            unsigned long long k = warp_key[lane];
            unsigned hb = (unsigned)(k >> 32);
            unsigned hm = __reduce_max_sync(0xffffffffu, hb);
            unsigned lo = (hb == hm) ? (unsigned)k : 0u;
            unsigned lm = __reduce_max_sync(0xffffffffu, lo);

            // ---- push {x,y,z,distbits} (16 B) to every CTA: lane t -> rank t ----
            if (lane < CLUSTER) {
                unsigned local = (~lm) & (PPC - 1);     // block winner, CTA-local
                float wx = xs[local], wy = ys[local], wz = zs[local];
                unsigned rslot = par ? rs1 : rs0;
                unsigned rbar  = par ? rb1 : rb0;
                st_async_u64(rslot,     packf2(wx, wy), rbar);
                st_async_u64(rslot + 8, pack_fu(wz, hm), rbar);
            }
        }

        // ---- ALL warps sleep on the mbarrier; each reduces the 8 slots ----
        mbar_wait(barp, par ? ph1 : ph0);

        float4 s = *(const float4*)&slotmem[par][lane & (CLUSTER - 1)][0];
        unsigned db = __float_as_uint(s.w);
        unsigned m  = __reduce_max_sync(0xffffffffu, db);
        // Cross-CTA tie-break: rank ranges contiguous ascending, so
        // min global index == min rank == min slot.
        unsigned bal = __ballot_sync(0xffffffffu, (lane < CLUSTER) && (db == m));
        unsigned winslot = (unsigned)(__ffs(bal) - 1);
        float4 w = *(const float4*)&slotmem[par][winslot][0];   // broadcast LDS

        nlx2 = packf2(-w.x, -w.x);
        nly2 = packf2(-w.y, -w.y);
        nlz2 = packf2(-w.z, -w.z);

        if (r == 0 && tid == 0) {
            ob[it] = w.x; ob[NPOINTS + it] = w.y; ob[2 * NPOINTS + it] = w.z;
        }
        if (par) ph1 ^= 1; else ph0 ^= 1;
    }
}

extern "C" void kernel_launch(void* const* d_in, const int* in_sizes, int n_in,
                              void* d_out, int out_size)
{
    const float* x = (const float*)d_in[0];
    float* out = (float*)d_out;
    int B = in_sizes[0] / (3 * N_PTS);   // 16
    size_t dyn = 3 * PPC * sizeof(float);   // 96 KB
    cudaFuncSetAttribute(fps_cluster_kernel,
                         cudaFuncAttributeMaxDynamicSharedMemorySize, (int)dyn);
    dim3 grid(B * CLUSTER), block(THREADS);
    fps_cluster_kernel<<<grid, block, dyn>>>(x, out);
}

// round 9
// speedup vs baseline: 1.4368x; 1.0090x over previous
#include <cuda_runtime.h>
#include <cstdint>

// FurthestPointsSample: x [B,3,N] f32 -> out [B,3,1024] f32. B=16, N=65536.
// 8-CTA cluster per batch; points register-resident (8/thread, packed f32x2)
// + SMEM mirror. Per round: f32x2 dist update, REDUX reductions, ONE vector
// st.async.v2.b64 (16 B) per destination CTA {x,y,z,distbits} on one mbarrier
// per parity (8 ingress events instead of 16), warp0-only wait + slot reduce +
// smem broadcast. Tie-break = slot position (contiguous rank index ranges).

#define N_PTS   65536
#define CLUSTER 8
#define PPC     (N_PTS / CLUSTER)   // 8192
#define THREADS 1024
#define PPT     (PPC / THREADS)     // 8
#define NPAIR   (PPT / 2)           // 4
#define NPOINTS 1024
#define MSG_TX  16                  // bytes per source CTA (one v2.b64 store)

__device__ __forceinline__ unsigned ctarank() {
    unsigned r; asm("mov.u32 %0, %%cluster_ctarank;" : "=r"(r)); return r;
}
__device__ __forceinline__ void cluster_sync_all() {
    asm volatile("barrier.cluster.arrive.aligned;\n\t"
                 "barrier.cluster.wait.aligned;" ::: "memory");
}
__device__ __forceinline__ unsigned mapa_sh(unsigned addr, unsigned rank) {
    unsigned r;
    asm("mapa.shared::cluster.u32 %0, %1, %2;" : "=r"(r) : "r"(addr), "r"(rank));
    return r;
}
__device__ __forceinline__ unsigned long long addx2(unsigned long long a, unsigned long long b) {
    unsigned long long r; asm("add.rn.f32x2 %0, %1, %2;" : "=l"(r) : "l"(a), "l"(b)); return r;
}
__device__ __forceinline__ unsigned long long mulx2(unsigned long long a, unsigned long long b) {
    unsigned long long r; asm("mul.rn.f32x2 %0, %1, %2;" : "=l"(r) : "l"(a), "l"(b)); return r;
}
__device__ __forceinline__ unsigned long long packf2(float lo, float hi) {
    unsigned long long r; asm("mov.b64 %0, {%1, %2};" : "=l"(r) : "f"(lo), "f"(hi)); return r;
}
__device__ __forceinline__ void unpackf2(unsigned long long v, float& lo, float& hi) {
    asm("mov.b64 {%0, %1}, %2;" : "=f"(lo), "=f"(hi) : "l"(v));
}
__device__ __forceinline__ unsigned long long pack_fu(float z, unsigned hi) {
    unsigned long long r; asm("mov.b64 %0, {%1, %2};" : "=l"(r) : "f"(z), "r"(hi)); return r;
}
// Single 16-byte vector st.async: one DSMEM ingress event per destination.
__device__ __forceinline__ void st_async_v2_u64(unsigned addr, unsigned long long a,
                                                unsigned long long c, unsigned mbar) {
    asm volatile("st.async.shared::cluster.mbarrier::complete_tx::bytes.v2.b64 [%0], {%1, %2}, [%3];"
                 :: "r"(addr), "l"(a), "l"(c), "r"(mbar) : "memory");
}
__device__ __forceinline__ void mbar_init(unsigned addr, unsigned cnt) {
    asm volatile("mbarrier.init.shared.b64 [%0], %1;" :: "r"(addr), "r"(cnt) : "memory");
}
__device__ __forceinline__ void mbar_expect_tx(unsigned addr, unsigned tx) {
    asm volatile("mbarrier.arrive.expect_tx.shared.b64 _, [%0], %1;"
                 :: "r"(addr), "r"(tx) : "memory");
}
__device__ __forceinline__ void mbar_wait(unsigned addr, unsigned phase) {
    asm volatile(
        "{\n\t.reg .pred P;\n\t"
        "LAB_%=:\n\t"
        "mbarrier.try_wait.parity.acquire.cta.shared::cta.b64 P, [%0], %1, 0x989680;\n\t"
        "@!P bra LAB_%=;\n\t}"
        :: "r"(addr), "r"(phase) : "memory");
}

extern __shared__ float smem_dyn[];   // xs[8192] ys[8192] zs[8192] = 96 KB

__global__ void __launch_bounds__(THREADS, 1) __cluster_dims__(CLUSTER, 1, 1)
fps_cluster_kernel(const float* __restrict__ x, float* __restrict__ out)
{
    __shared__ unsigned long long warp_key[32];
    // 16-byte slots: [x f32][y f32][z f32][distbits u32]
    __shared__ __align__(16) float slotmem[2][CLUSTER][4];
    __shared__ float4 bcast[2];
    __shared__ __align__(8) unsigned long long mbar[2];

    const unsigned r    = ctarank();
    const unsigned b    = blockIdx.x / CLUSTER;
    const unsigned tid  = threadIdx.x;
    const unsigned lane = tid & 31u;
    const unsigned wid  = tid >> 5;

    const float* __restrict__ xb = x + (size_t)b * 3u * N_PTS;
    const float* __restrict__ yb = xb + N_PTS;
    const float* __restrict__ zb = xb + 2 * N_PTS;
    float* __restrict__ ob = out + (size_t)b * 3u * NPOINTS;

    float* xs = smem_dyn;
    float* ys = xs + PPC;
    float* zs = ys + PPC;

    const unsigned slot_base = (unsigned)__cvta_generic_to_shared(&slotmem[0][0][0]);
    const unsigned bar_base  = (unsigned)__cvta_generic_to_shared(&mbar[0]);

    if (tid == 0) { mbar_init(bar_base, 1); mbar_init(bar_base + 8, 1); }

    // Hoisted remote addresses (lane t < 8 targets rank t; my slot index = r).
    unsigned rs0 = 0, rs1 = 0, rb0 = 0, rb1 = 0;
    if (lane < CLUSTER) {
        rs0 = mapa_sh(slot_base + (0 * CLUSTER + r) * 16u, lane);
        rs1 = mapa_sh(slot_base + (1 * CLUSTER + r) * 16u, lane);
        rb0 = mapa_sh(bar_base,      lane);
        rb1 = mapa_sh(bar_base + 8u, lane);
    }

    // Load points into registers (packed pairs) + SMEM mirror.
    unsigned long long px2[NPAIR], py2[NPAIR], pz2[NPAIR];
    float dist[PPT];
    const unsigned gbase = r * PPC + tid;
#pragma unroll
    for (int p = 0; p < NPAIR; p++) {
        unsigned g0 = gbase + (unsigned)(2 * p) * THREADS;
        unsigned g1 = g0 + THREADS;
        float x0 = xb[g0], x1 = xb[g1];
        float y0 = yb[g0], y1 = yb[g1];
        float z0 = zb[g0], z1 = zb[g1];
        px2[p] = packf2(x0, x1); py2[p] = packf2(y0, y1); pz2[p] = packf2(z0, z1);
        unsigned l0 = tid + (unsigned)(2 * p) * THREADS, l1 = l0 + THREADS;
        xs[l0] = x0; xs[l1] = x1; ys[l0] = y0; ys[l1] = y1; zs[l0] = z0; zs[l1] = z1;
        dist[2 * p] = 1e10f; dist[2 * p + 1] = 1e10f;
    }
    __syncthreads();
    cluster_sync_all();   // peers' mbarriers initialized before any st.async

    // First selected point: index 0 (reference convention).
    float fx = __ldg(xb + 0), fy = __ldg(yb + 0), fz = __ldg(zb + 0);
    if (r == 0 && tid == 0) { ob[0] = fx; ob[NPOINTS] = fy; ob[2 * NPOINTS] = fz; }
    unsigned long long nlx2 = packf2(-fx, -fx);
    unsigned long long nly2 = packf2(-fy, -fy);
    unsigned long long nlz2 = packf2(-fz, -fz);

    unsigned ph0 = 0, ph1 = 0;

    for (int it = 1; it < NPOINTS; it++) {
        const int par = it & 1;
        const unsigned barp = bar_base + (unsigned)par * 8u;

        // Arm this round's barrier early (off the critical tail).
        if (tid == 0) mbar_expect_tx(barp, CLUSTER * MSG_TX);

        // ---- dist update + thread-local argmax (bit-exact, first occurrence) ----
        float bestd = -1.0f; int bestj = 0;
#pragma unroll
        for (int p = 0; p < NPAIR; p++) {
            unsigned long long dx = addx2(px2[p], nlx2);
            unsigned long long dy = addx2(py2[p], nly2);
            unsigned long long dz = addx2(pz2[p], nlz2);
            unsigned long long s  = addx2(addx2(mulx2(dx, dx), mulx2(dy, dy)), mulx2(dz, dz));
            float s0, s1; unpackf2(s, s0, s1);
            float nd0 = fminf(dist[2 * p], s0);     dist[2 * p]     = nd0;
            float nd1 = fminf(dist[2 * p + 1], s1); dist[2 * p + 1] = nd1;
            bool c0 = nd0 > bestd; bestd = c0 ? nd0 : bestd; bestj = c0 ? 2 * p : bestj;
            bool c1 = nd1 > bestd; bestd = c1 ? nd1 : bestd; bestj = c1 ? 2 * p + 1 : bestj;
        }

        // ---- warp reduction: max dist bits, then min global index ----
        unsigned bits = __float_as_uint(bestd);
        unsigned wmax = __reduce_max_sync(0xffffffffu, bits);
        unsigned g    = gbase + (unsigned)bestj * THREADS;
        unsigned cand = (bits == wmax) ? ~g : 0u;
        unsigned wi   = __reduce_max_sync(0xffffffffu, cand);
        if (lane == 0)
            warp_key[wid] = ((unsigned long long)wmax << 32) | wi;
        __syncthreads();

        if (wid == 0) {
            // ---- block reduction over 32 warp keys ----
            unsigned long long k = warp_key[lane];
            unsigned hb = (unsigned)(k >> 32);
            unsigned hm = __reduce_max_sync(0xffffffffu, hb);
            unsigned lo = (hb == hm) ? (unsigned)k : 0u;
            unsigned lm = __reduce_max_sync(0xffffffffu, lo);

            // ---- ONE 16-B vector push {x,y,z,distbits} to every CTA ----
            if (lane < CLUSTER) {
                unsigned local = (~lm) & (PPC - 1);     // block winner, CTA-local
                float wx = xs[local], wy = ys[local], wz = zs[local];
                unsigned rslot = par ? rs1 : rs0;
                unsigned rbar  = par ? rb1 : rb0;
                st_async_v2_u64(rslot, packf2(wx, wy), pack_fu(wz, hm), rbar);
            }

            // ---- warp0 waits for all 8 messages, reduces the slots ----
            mbar_wait(barp, par ? ph1 : ph0);

            float4 s = *(const float4*)&slotmem[par][lane & (CLUSTER - 1)][0];
            unsigned db = __float_as_uint(s.w);
            unsigned m  = __reduce_max_sync(0xffffffffu, db);
            // Cross-CTA tie-break: rank ranges contiguous ascending, so
            // min global index == min rank == min slot == min lane here.
            unsigned bal = __ballot_sync(0xffffffffu, (lane < CLUSTER) && (db == m));
            if (lane == (unsigned)(__ffs(bal) - 1)) {
                bcast[par] = s;
                if (r == 0) {
                    ob[it] = s.x; ob[NPOINTS + it] = s.y; ob[2 * NPOINTS + it] = s.z;
                }
            }
        }
        __syncthreads();

        float4 w = bcast[par];
        nlx2 = packf2(-w.x, -w.x);
        nly2 = packf2(-w.y, -w.y);
        nlz2 = packf2(-w.z, -w.z);
        if (par) ph1 ^= 1; else ph0 ^= 1;
    }
}

extern "C" void kernel_launch(void* const* d_in, const int* in_sizes, int n_in,
                              void* d_out, int out_size)
{
    const float* x = (const float*)d_in[0];
    float* out = (float*)d_out;
    int B = in_sizes[0] / (3 * N_PTS);   // 16
    size_t dyn = 3 * PPC * sizeof(float);   // 96 KB
    cudaFuncSetAttribute(fps_cluster_kernel,
                         cudaFuncAttributeMaxDynamicSharedMemorySize, (int)dyn);
    dim3 grid(B * CLUSTER), block(THREADS);
    fps_cluster_kernel<<<grid, block, dyn>>>(x, out);
}